// round 2
// baseline (speedup 1.0000x reference)
#include <cuda_runtime.h>
#include <cuda_fp16.h>
#include <stdint.h>

// ============================================================================
// FibonacciKAN: y[b,o] = sum_i sum_d F_d(tanh(x[b,i])) * C[i,o,d]
// Monomial re-expansion:
//   poly(t) = (C1+C3+C5) + (C2+2C4) t + (C3+3C5) t^2 + C4 t^3 + C5 t^4
// => Y = A @ W + bias, A[32768, 1024] = powers(tanh(x)), W[1024,256], fp16/fp32acc
// ============================================================================

#define B_ROWS 32768
#define IN_DIM 256
#define OUT_DIM 256
#define KDIM 1024          // IN_DIM * 4 monomial powers

#define BM 128
#define BN 256
#define BK 32
#define APAD 8             // As row = BK+APAD = 40 halves = 80B (conflict-free frag loads)
#define WPAD 4             // Ws row = BK+WPAD = 36 halves = 72B

// W stored [o][k] (o-major) so B-fragment loads are contiguous along k.
__device__ __half g_W[OUT_DIM * KDIM];
__device__ float  g_bias[OUT_DIM];

// ----------------------------------------------------------------------------
// Weight prep: C[i][o][d] (i<256, o<256, d<6) -> monomial W + bias
// grid: 256 blocks (o), 256 threads (i)
// ----------------------------------------------------------------------------
__global__ void prep_weights_kernel(const float* __restrict__ C) {
    int o = blockIdx.x;
    int i = threadIdx.x;
    const float* c = C + ((size_t)i * OUT_DIM + o) * 6;
    float c1 = c[1], c2 = c[2], c3 = c[3], c4 = c[4], c5 = c[5];
    float w1 = c2 + 2.0f * c4;   // * t
    float w2 = c3 + 3.0f * c5;   // * t^2
    float w3 = c4;               // * t^3
    float w4 = c5;               // * t^4

    __half2* dst = (__half2*)(g_W + (size_t)o * KDIM + i * 4);
    dst[0] = __floats2half2_rn(w1, w2);
    dst[1] = __floats2half2_rn(w3, w4);

    // bias[o] = sum_i (c1 + c3 + c5)
    __shared__ float sb[256];
    sb[i] = c1 + c3 + c5;
    __syncthreads();
    #pragma unroll
    for (int s = 128; s > 0; s >>= 1) {
        if (i < s) sb[i] += sb[i + s];
        __syncthreads();
    }
    if (i == 0) g_bias[o] = sb[0];
}

// ----------------------------------------------------------------------------
// Fused GEMM: builds A tiles (tanh + powers, fp16) in SMEM on the fly,
// mma.sync.m16n8k16 f16 x f16 -> f32.
// 512 threads = 16 warps in a 4x4 grid of 32x64 warp tiles. BM=128, BN=256.
// ----------------------------------------------------------------------------
__global__ __launch_bounds__(512, 1)
void kan_gemm_kernel(const float* __restrict__ X, float* __restrict__ Y) {
    __shared__ __half As[BM][BK + APAD];   // 128 x 40 halves = 10 KB
    __shared__ __half Ws[BN][BK + WPAD];   // 256 x 36 halves = 18 KB

    const int tid  = threadIdx.x;
    const int warp = tid >> 5;
    const int lane = tid & 31;
    const int wr = warp >> 2;          // warp row 0..3  (32 rows each)
    const int wc = warp & 3;           // warp col 0..3  (64 cols each)
    const int g   = lane >> 2;         // group id 0..7
    const int tig = lane & 3;          // thread-in-group 0..3
    const int rowbase = blockIdx.x * BM;

    float acc[2][8][4];
    #pragma unroll
    for (int mt = 0; mt < 2; ++mt)
        #pragma unroll
        for (int nt = 0; nt < 8; ++nt)
            #pragma unroll
            for (int q = 0; q < 4; ++q) acc[mt][nt][q] = 0.0f;

    for (int kt = 0; kt < KDIM / BK; ++kt) {   // 32 iterations
        // ---- stage A: 128 rows x 8 input channels -> powers of tanh ----
        const int ch0 = kt * 8;
        #pragma unroll
        for (int j = 0; j < 2; ++j) {
            int e = tid + j * 512;        // 0..1023
            int r = e >> 3;
            int c = e & 7;
            float xv = X[(size_t)(rowbase + r) * IN_DIM + ch0 + c];
            float t  = tanhf(xv);
            float t2 = t * t, t3 = t2 * t, t4 = t2 * t2;
            __half2* dst = (__half2*)&As[r][c * 4];
            dst[0] = __floats2half2_rn(t,  t2);
            dst[1] = __floats2half2_rn(t3, t4);
        }
        // ---- stage W: 256 cols x 32 k (from L2-resident g_W) ----
        #pragma unroll
        for (int j = 0; j < 4; ++j) {
            int u = tid + j * 512;        // 0..2047
            int n = u >> 3;
            int seg = u & 7;              // 8 x uint2 (4 halves) per row
            const uint2* src = (const uint2*)(g_W + (size_t)n * KDIM + kt * BK + seg * 4);
            *(uint2*)&Ws[n][seg * 4] = *src;
        }
        __syncthreads();

        // ---- compute: 2 k-steps of 16 ----
        #pragma unroll
        for (int kk = 0; kk < 2; ++kk) {
            const int kb = kk * 16;
            uint32_t a[2][4];
            #pragma unroll
            for (int mt = 0; mt < 2; ++mt) {
                int r = wr * 32 + mt * 16;
                a[mt][0] = *(const uint32_t*)&As[r + g    ][kb + tig * 2    ];
                a[mt][1] = *(const uint32_t*)&As[r + g + 8][kb + tig * 2    ];
                a[mt][2] = *(const uint32_t*)&As[r + g    ][kb + tig * 2 + 8];
                a[mt][3] = *(const uint32_t*)&As[r + g + 8][kb + tig * 2 + 8];
            }
            #pragma unroll
            for (int nt = 0; nt < 8; ++nt) {
                int n = wc * 64 + nt * 8 + g;
                uint32_t b0 = *(const uint32_t*)&Ws[n][kb + tig * 2    ];
                uint32_t b1 = *(const uint32_t*)&Ws[n][kb + tig * 2 + 8];
                #pragma unroll
                for (int mt = 0; mt < 2; ++mt) {
                    asm volatile(
                        "mma.sync.aligned.m16n8k16.row.col.f32.f16.f16.f32 "
                        "{%0,%1,%2,%3}, {%4,%5,%6,%7}, {%8,%9}, {%0,%1,%2,%3};\n"
                        : "+f"(acc[mt][nt][0]), "+f"(acc[mt][nt][1]),
                          "+f"(acc[mt][nt][2]), "+f"(acc[mt][nt][3])
                        : "r"(a[mt][0]), "r"(a[mt][1]), "r"(a[mt][2]), "r"(a[mt][3]),
                          "r"(b0), "r"(b1));
                }
            }
        }
        __syncthreads();
    }

    // ---- epilogue: + bias, fp32 store ----
    #pragma unroll
    for (int mt = 0; mt < 2; ++mt) {
        int r0 = rowbase + wr * 32 + mt * 16;
        #pragma unroll
        for (int nt = 0; nt < 8; ++nt) {
            int c0 = wc * 64 + nt * 8 + tig * 2;
            float b0 = g_bias[c0];
            float b1 = g_bias[c0 + 1];
            int r = r0 + g;
            Y[(size_t)r * OUT_DIM + c0]           = acc[mt][nt][0] + b0;
            Y[(size_t)r * OUT_DIM + c0 + 1]       = acc[mt][nt][1] + b1;
            Y[(size_t)(r + 8) * OUT_DIM + c0]     = acc[mt][nt][2] + b0;
            Y[(size_t)(r + 8) * OUT_DIM + c0 + 1] = acc[mt][nt][3] + b1;
        }
    }
}

// ----------------------------------------------------------------------------
extern "C" void kernel_launch(void* const* d_in, const int* in_sizes, int n_in,
                              void* d_out, int out_size) {
    // inputs: x [32768,256] f32, fib_coeffs [256,256,6] f32 (defensive order check)
    const float* x = (const float*)d_in[0];
    const float* coeffs = (const float*)d_in[1];
    if (n_in >= 2 && in_sizes[0] == OUT_DIM * IN_DIM * 6) {  // swapped order
        coeffs = (const float*)d_in[0];
        x = (const float*)d_in[1];
    }
    float* y = (float*)d_out;

    prep_weights_kernel<<<OUT_DIM, IN_DIM>>>(coeffs);
    kan_gemm_kernel<<<B_ROWS / BM, 512>>>(x, y);
}

// round 6
// speedup vs baseline: 1.5878x; 1.5878x over previous
#include <cuda_runtime.h>
#include <cuda_fp16.h>
#include <stdint.h>

// ============================================================================
// FibonacciKAN via monomial re-expansion, legacy mma.sync path (tcgen05 is
// unavailable: harness PTX targets compute_103, all tcgen05 ops are 'a'-gated).
//   poly(t) = bias + w1 t + w2 t^2 + w3 t^3 + w4 t^4,  t = tanh(x)
//   Y[32768,256] = A[32768,1024] @ W[1024,256] + bias
// Per CTA: 128x256 tile, K=1024, BK=64, double-buffered cp.async pipeline,
// ldmatrix fragment loads, 16 warps (4x4 grid of 32x64 warp tiles).
// ============================================================================

#define B_ROWS 32768
#define IN_DIM 256
#define OUT_DIM 256
#define KDIM 1024
#define BM 128
#define BN 256
#define BK 64                 // halves per K tile = 16 input channels * 4 powers
#define NKT (KDIM / BK)       // 16
#define NTHREADS 512

#define SA 72                 // A row stride in halves (144 B) -> conflict-free
#define SWROW 72              // W row stride in halves
#define ABYTES (BM * SA * 2)      // 18432
#define WBYTES (BN * SWROW * 2)   // 36864
#define SM_A0 0
#define SM_A1 (SM_A0 + ABYTES)
#define SM_W0 (SM_A1 + ABYTES)
#define SM_W1 (SM_W0 + WBYTES)
#define SM_TOTAL (SM_W1 + WBYTES)   // 110592 bytes

__device__ __half g_W[OUT_DIM * KDIM];   // [o][k], k-contiguous
__device__ float  g_bias[OUT_DIM];

// ---------------------------------------------------------------------------
__device__ __forceinline__ uint32_t smem_u32(const void* p) {
    uint32_t a;
    asm("{ .reg .u64 t; cvta.to.shared.u64 t, %1; cvt.u32.u64 %0, t; }"
        : "=r"(a) : "l"(p));
    return a;
}
__device__ __forceinline__ void cp_async16(uint32_t dst, const void* src) {
    asm volatile("cp.async.cg.shared.global [%0], [%1], 16;"
                 :: "r"(dst), "l"(src) : "memory");
}
__device__ __forceinline__ void cp_commit() {
    asm volatile("cp.async.commit_group;" ::: "memory");
}
__device__ __forceinline__ void cp_wait0() {
    asm volatile("cp.async.wait_group 0;" ::: "memory");
}
__device__ __forceinline__ void ldsm_x4(uint32_t& r0, uint32_t& r1,
                                        uint32_t& r2, uint32_t& r3, uint32_t addr) {
    asm volatile("ldmatrix.sync.aligned.m8n8.x4.shared.b16 {%0,%1,%2,%3}, [%4];"
                 : "=r"(r0), "=r"(r1), "=r"(r2), "=r"(r3) : "r"(addr));
}
__device__ __forceinline__ uint32_t pack_h2(float a, float b) {
    __half2 h = __floats2half2_rn(a, b);
    return *(uint32_t*)&h;
}

// ---------------------------------------------------------------------------
// Weight prep: C[i][o][d] -> monomial W[o][k=i*4+p] fp16 + bias[o]
// ---------------------------------------------------------------------------
__global__ void prep_weights_kernel(const float* __restrict__ C) {
    int o = blockIdx.x;
    int i = threadIdx.x;
    const float* c = C + ((size_t)i * OUT_DIM + o) * 6;
    float c1 = c[1], c2 = c[2], c3 = c[3], c4 = c[4], c5 = c[5];
    __half2* dst = (__half2*)(g_W + (size_t)o * KDIM + i * 4);
    dst[0] = __floats2half2_rn(c2 + 2.0f * c4, c3 + 3.0f * c5);
    dst[1] = __floats2half2_rn(c4, c5);

    __shared__ float sb[256];
    sb[i] = c1 + c3 + c5;
    __syncthreads();
    #pragma unroll
    for (int s = 128; s > 0; s >>= 1) {
        if (i < s) sb[i] += sb[i + s];
        __syncthreads();
    }
    if (i == 0) g_bias[o] = sb[0];
}

// ---------------------------------------------------------------------------
// Fused pipelined GEMM
// ---------------------------------------------------------------------------
__global__ __launch_bounds__(NTHREADS, 1)
void kan_gemm_kernel(const float* __restrict__ X, float* __restrict__ Y) {
    extern __shared__ char smem[];
    const uint32_t sbase = smem_u32(smem);
    const int tid  = threadIdx.x;
    const int warp = tid >> 5;
    const int lane = tid & 31;
    const int wr = warp >> 2;           // 0..3
    const int wc = warp & 3;            // 0..3
    const int g  = lane >> 2;
    const int tig = lane & 3;
    const int rowbase = blockIdx.x * BM;

    // A staging geometry: thread -> (row, group of 4 input channels)
    const int arow = tid >> 2;          // 0..127
    const int agrp = tid & 3;           // 0..3
    const float* xptr = X + (size_t)(rowbase + arow) * IN_DIM + agrp * 4;
    const uint32_t ast = (uint32_t)arow * (SA * 2) + (uint32_t)agrp * 32;

    // W staging geometry: 2048 16B chunks, 4 per thread
    const int wrow0 = tid >> 3;         // 0..63 (+64 per j)
    const int wseg  = tid & 7;          // 0..7

    // ldmatrix per-thread base offsets (bytes)
    const uint32_t a_lds = (uint32_t)(wr * 32 + (lane & 7) + ((lane >> 3) & 1) * 8)
                           * (SA * 2) + ((lane >> 4) & 1) * 16;
    const uint32_t b_lds = (uint32_t)(wc * 64 + (lane & 7) + ((lane >> 4) & 1) * 8)
                           * (SWROW * 2) + ((lane >> 3) & 1) * 16;

    float acc[2][8][4];
    #pragma unroll
    for (int mt = 0; mt < 2; ++mt)
        #pragma unroll
        for (int nt = 0; nt < 8; ++nt)
            #pragma unroll
            for (int q = 0; q < 4; ++q) acc[mt][nt][q] = 0.0f;

    // ---- prologue: stage tile 0 into buffer 0 ----
    {
        // W tile 0 via cp.async
        #pragma unroll
        for (int j = 0; j < 4; ++j) {
            int nrow = wrow0 + j * 64;
            cp_async16(sbase + SM_W0 + (uint32_t)nrow * (SWROW * 2) + wseg * 16,
                       g_W + (size_t)nrow * KDIM + wseg * 8);
        }
        cp_commit();
        // A tile 0: tanh powers
        float4 xv = *(const float4*)xptr;
        float t0 = tanhf(xv.x), t1 = tanhf(xv.y), t2 = tanhf(xv.z), t3 = tanhf(xv.w);
        float s0 = t0*t0, s1 = t1*t1, s2 = t2*t2, s3 = t3*t3;
        uint4 c01, c23;
        c01.x = pack_h2(t0, s0); c01.y = pack_h2(s0*t0, s0*s0);
        c01.z = pack_h2(t1, s1); c01.w = pack_h2(s1*t1, s1*s1);
        c23.x = pack_h2(t2, s2); c23.y = pack_h2(s2*t2, s2*s2);
        c23.z = pack_h2(t3, s3); c23.w = pack_h2(s3*t3, s3*s3);
        *(uint4*)(smem + SM_A0 + ast)      = c01;
        *(uint4*)(smem + SM_A0 + ast + 16) = c23;
    }

    for (int kt = 0; kt < NKT; ++kt) {
        const int cur = kt & 1;
        const uint32_t Ab = sbase + (cur ? SM_A1 : SM_A0);
        const uint32_t Wb = sbase + (cur ? SM_W1 : SM_W0);
        const uint32_t Abn = sbase + (cur ? SM_A0 : SM_A1);
        const uint32_t Wbn = sbase + (cur ? SM_W0 : SM_W1);

        // prefetch X for next tile into registers (hides DRAM latency under MMA)
        float4 xv;
        if (kt + 1 < NKT) xv = *(const float4*)(xptr + (kt + 1) * 16);

        cp_wait0();            // W tile kt landed
        __syncthreads();       // A tile kt visible; buffer nxt free

        // issue cp.async for W tile kt+1 (after barrier: nxt no longer being read)
        if (kt + 1 < NKT) {
            #pragma unroll
            for (int j = 0; j < 4; ++j) {
                int nrow = wrow0 + j * 64;
                cp_async16(Wbn + (uint32_t)nrow * (SWROW * 2) + wseg * 16,
                           g_W + (size_t)nrow * KDIM + (kt + 1) * BK + wseg * 8);
            }
            cp_commit();
        }

        // ---- MMAs on tile kt: 4 k-steps of 16 ----
        #pragma unroll
        for (int kk = 0; kk < 4; ++kk) {
            uint32_t a[2][4];
            #pragma unroll
            for (int mt = 0; mt < 2; ++mt)
                ldsm_x4(a[mt][0], a[mt][1], a[mt][2], a[mt][3],
                        Ab + a_lds + mt * 16 * (SA * 2) + kk * 32);
            #pragma unroll
            for (int ntp = 0; ntp < 4; ++ntp) {
                uint32_t b[4];
                ldsm_x4(b[0], b[1], b[2], b[3],
                        Wb + b_lds + ntp * 16 * (SWROW * 2) + kk * 32);
                #pragma unroll
                for (int h = 0; h < 2; ++h) {       // two n-tiles per ldmatrix
                    const int nt = ntp * 2 + h;
                    #pragma unroll
                    for (int mt = 0; mt < 2; ++mt) {
                        asm volatile(
                            "mma.sync.aligned.m16n8k16.row.col.f32.f16.f16.f32 "
                            "{%0,%1,%2,%3}, {%4,%5,%6,%7}, {%8,%9}, {%0,%1,%2,%3};\n"
                            : "+f"(acc[mt][nt][0]), "+f"(acc[mt][nt][1]),
                              "+f"(acc[mt][nt][2]), "+f"(acc[mt][nt][3])
                            : "r"(a[mt][0]), "r"(a[mt][1]), "r"(a[mt][2]), "r"(a[mt][3]),
                              "r"(b[h * 2]), "r"(b[h * 2 + 1]));
                    }
                }
            }
        }

        // ---- stage A tile kt+1 (into nxt buffer; others are MMAing cur) ----
        if (kt + 1 < NKT) {
            float t0 = tanhf(xv.x), t1 = tanhf(xv.y), t2 = tanhf(xv.z), t3 = tanhf(xv.w);
            float s0 = t0*t0, s1 = t1*t1, s2 = t2*t2, s3 = t3*t3;
            uint4 c01, c23;
            c01.x = pack_h2(t0, s0); c01.y = pack_h2(s0*t0, s0*s0);
            c01.z = pack_h2(t1, s1); c01.w = pack_h2(s1*t1, s1*s1);
            c23.x = pack_h2(t2, s2); c23.y = pack_h2(s2*t2, s2*s2);
            c23.z = pack_h2(t3, s3); c23.w = pack_h2(s3*t3, s3*s3);
            *(uint4*)((char*)smem + (Abn - sbase) + ast)      = c01;
            *(uint4*)((char*)smem + (Abn - sbase) + ast + 16) = c23;
        }
    }

    // ---- epilogue: + bias, fp32 store ----
    #pragma unroll
    for (int mt = 0; mt < 2; ++mt) {
        int r0 = rowbase + wr * 32 + mt * 16;
        #pragma unroll
        for (int nt = 0; nt < 8; ++nt) {
            int c0 = wc * 64 + nt * 8 + tig * 2;
            float b0 = __ldg(&g_bias[c0]);
            float b1 = __ldg(&g_bias[c0 + 1]);
            int r = r0 + g;
            float2 lo = make_float2(acc[mt][nt][0] + b0, acc[mt][nt][1] + b1);
            float2 hi = make_float2(acc[mt][nt][2] + b0, acc[mt][nt][3] + b1);
            *(float2*)(Y + (size_t)r * OUT_DIM + c0)       = lo;
            *(float2*)(Y + (size_t)(r + 8) * OUT_DIM + c0) = hi;
        }
    }
}

// ---------------------------------------------------------------------------
extern "C" void kernel_launch(void* const* d_in, const int* in_sizes, int n_in,
                              void* d_out, int out_size) {
    const float* x = (const float*)d_in[0];
    const float* coeffs = (const float*)d_in[1];
    if (n_in >= 2 && in_sizes[0] == OUT_DIM * IN_DIM * 6) {  // defensive order check
        coeffs = (const float*)d_in[0];
        x = (const float*)d_in[1];
    }
    float* y = (float*)d_out;

    static bool attr_set = false;
    if (!attr_set) {
        cudaFuncSetAttribute(kan_gemm_kernel,
                             cudaFuncAttributeMaxDynamicSharedMemorySize, SM_TOTAL);
        attr_set = true;
    }

    prep_weights_kernel<<<OUT_DIM, IN_DIM>>>(coeffs);
    kan_gemm_kernel<<<B_ROWS / BM, NTHREADS, SM_TOTAL>>>(x, y);
}

// round 7
// speedup vs baseline: 1.6689x; 1.0511x over previous
#include <cuda_runtime.h>
#include <cuda_fp16.h>
#include <stdint.h>

// ============================================================================
// FibonacciKAN via monomial re-expansion, legacy mma.sync path (tcgen05 is
// unavailable: harness PTX targets compute_103, all tcgen05 ops are 'a'-gated).
//   poly(t) = bias + w1 t + w2 t^2 + w3 t^3 + w4 t^4,  t = tanh(x)
//   Y[32768,256] = A[32768,1024] @ W[1024,256] + bias
// R6: tanhf -> tanh.approx.f32 (1 MUFU vs 2 MUFU + ~15 FMA). The hidden xu-pipe
// load of libm tanhf was co-binding with the tensor pipe.
// ============================================================================

#define B_ROWS 32768
#define IN_DIM 256
#define OUT_DIM 256
#define KDIM 1024
#define BM 128
#define BN 256
#define BK 64                 // halves per K tile = 16 input channels * 4 powers
#define NKT (KDIM / BK)       // 16
#define NTHREADS 512

#define SA 72                 // A row stride in halves (144 B) -> conflict-free
#define SWROW 72              // W row stride in halves
#define ABYTES (BM * SA * 2)      // 18432
#define WBYTES (BN * SWROW * 2)   // 36864
#define SM_A0 0
#define SM_A1 (SM_A0 + ABYTES)
#define SM_W0 (SM_A1 + ABYTES)
#define SM_W1 (SM_W0 + WBYTES)
#define SM_TOTAL (SM_W1 + WBYTES)   // 110592 bytes

__device__ __half g_W[OUT_DIM * KDIM];   // [o][k], k-contiguous
__device__ float  g_bias[OUT_DIM];

// ---------------------------------------------------------------------------
__device__ __forceinline__ uint32_t smem_u32(const void* p) {
    uint32_t a;
    asm("{ .reg .u64 t; cvta.to.shared.u64 t, %1; cvt.u32.u64 %0, t; }"
        : "=r"(a) : "l"(p));
    return a;
}
__device__ __forceinline__ void cp_async16(uint32_t dst, const void* src) {
    asm volatile("cp.async.cg.shared.global [%0], [%1], 16;"
                 :: "r"(dst), "l"(src) : "memory");
}
__device__ __forceinline__ void cp_commit() {
    asm volatile("cp.async.commit_group;" ::: "memory");
}
__device__ __forceinline__ void cp_wait0() {
    asm volatile("cp.async.wait_group 0;" ::: "memory");
}
__device__ __forceinline__ void ldsm_x4(uint32_t& r0, uint32_t& r1,
                                        uint32_t& r2, uint32_t& r3, uint32_t addr) {
    asm volatile("ldmatrix.sync.aligned.m8n8.x4.shared.b16 {%0,%1,%2,%3}, [%4];"
                 : "=r"(r0), "=r"(r1), "=r"(r2), "=r"(r3) : "r"(addr));
}
__device__ __forceinline__ uint32_t pack_h2(float a, float b) {
    __half2 h = __floats2half2_rn(a, b);
    return *(uint32_t*)&h;
}
__device__ __forceinline__ float tanh_fast(float x) {
    float y;
    asm("tanh.approx.f32 %0, %1;" : "=f"(y) : "f"(x));
    return y;
}

// ---------------------------------------------------------------------------
// Weight prep: C[i][o][d] -> monomial W[o][k=i*4+p] fp16 + bias[o]
// ---------------------------------------------------------------------------
__global__ void prep_weights_kernel(const float* __restrict__ C) {
    int o = blockIdx.x;
    int i = threadIdx.x;
    const float* c = C + ((size_t)i * OUT_DIM + o) * 6;
    float c1 = c[1], c2 = c[2], c3 = c[3], c4 = c[4], c5 = c[5];
    __half2* dst = (__half2*)(g_W + (size_t)o * KDIM + i * 4);
    dst[0] = __floats2half2_rn(c2 + 2.0f * c4, c3 + 3.0f * c5);
    dst[1] = __floats2half2_rn(c4, c5);

    // bias[o] = sum_i (c1 + c3 + c5): warp shuffle + tiny smem reduce
    float v = c1 + c3 + c5;
    #pragma unroll
    for (int s = 16; s > 0; s >>= 1)
        v += __shfl_xor_sync(0xFFFFFFFF, v, s);
    __shared__ float sb[8];
    if ((i & 31) == 0) sb[i >> 5] = v;
    __syncthreads();
    if (i < 8) {
        float w = sb[i];
        #pragma unroll
        for (int s = 4; s > 0; s >>= 1)
            w += __shfl_xor_sync(0xFF, w, s);
        if (i == 0) g_bias[o] = w;
    }
}

// ---------------------------------------------------------------------------
// Fused pipelined GEMM
// ---------------------------------------------------------------------------
__global__ __launch_bounds__(NTHREADS, 1)
void kan_gemm_kernel(const float* __restrict__ X, float* __restrict__ Y) {
    extern __shared__ char smem[];
    const uint32_t sbase = smem_u32(smem);
    const int tid  = threadIdx.x;
    const int warp = tid >> 5;
    const int lane = tid & 31;
    const int wr = warp >> 2;           // 0..3
    const int wc = warp & 3;            // 0..3
    const int g  = lane >> 2;
    const int tig = lane & 3;
    const int rowbase = blockIdx.x * BM;

    // A staging geometry: thread -> (row, group of 4 input channels)
    const int arow = tid >> 2;          // 0..127
    const int agrp = tid & 3;           // 0..3
    const float* xptr = X + (size_t)(rowbase + arow) * IN_DIM + agrp * 4;
    const uint32_t ast = (uint32_t)arow * (SA * 2) + (uint32_t)agrp * 32;

    // W staging geometry: 2048 16B chunks, 4 per thread
    const int wrow0 = tid >> 3;         // 0..63 (+64 per j)
    const int wseg  = tid & 7;          // 0..7

    // ldmatrix per-thread base offsets (bytes)
    const uint32_t a_lds = (uint32_t)(wr * 32 + (lane & 7) + ((lane >> 3) & 1) * 8)
                           * (SA * 2) + ((lane >> 4) & 1) * 16;
    const uint32_t b_lds = (uint32_t)(wc * 64 + (lane & 7) + ((lane >> 4) & 1) * 8)
                           * (SWROW * 2) + ((lane >> 3) & 1) * 16;

    float acc[2][8][4];
    #pragma unroll
    for (int mt = 0; mt < 2; ++mt)
        #pragma unroll
        for (int nt = 0; nt < 8; ++nt)
            #pragma unroll
            for (int q = 0; q < 4; ++q) acc[mt][nt][q] = 0.0f;

    // ---- prologue: stage tile 0 into buffer 0 ----
    {
        #pragma unroll
        for (int j = 0; j < 4; ++j) {
            int nrow = wrow0 + j * 64;
            cp_async16(sbase + SM_W0 + (uint32_t)nrow * (SWROW * 2) + wseg * 16,
                       g_W + (size_t)nrow * KDIM + wseg * 8);
        }
        cp_commit();
        float4 xv = *(const float4*)xptr;
        float t0 = tanh_fast(xv.x), t1 = tanh_fast(xv.y);
        float t2 = tanh_fast(xv.z), t3 = tanh_fast(xv.w);
        float s0 = t0*t0, s1 = t1*t1, s2 = t2*t2, s3 = t3*t3;
        uint4 c01, c23;
        c01.x = pack_h2(t0, s0); c01.y = pack_h2(s0*t0, s0*s0);
        c01.z = pack_h2(t1, s1); c01.w = pack_h2(s1*t1, s1*s1);
        c23.x = pack_h2(t2, s2); c23.y = pack_h2(s2*t2, s2*s2);
        c23.z = pack_h2(t3, s3); c23.w = pack_h2(s3*t3, s3*s3);
        *(uint4*)(smem + SM_A0 + ast)      = c01;
        *(uint4*)(smem + SM_A0 + ast + 16) = c23;
    }

    for (int kt = 0; kt < NKT; ++kt) {
        const int cur = kt & 1;
        const uint32_t Ab = sbase + (cur ? SM_A1 : SM_A0);
        const uint32_t Wb = sbase + (cur ? SM_W1 : SM_W0);
        const uint32_t Abn = sbase + (cur ? SM_A0 : SM_A1);
        const uint32_t Wbn = sbase + (cur ? SM_W0 : SM_W1);

        // prefetch X for next tile into registers (hides DRAM latency under MMA)
        float4 xv;
        if (kt + 1 < NKT) xv = *(const float4*)(xptr + (kt + 1) * 16);

        cp_wait0();            // W tile kt landed
        __syncthreads();       // A tile kt visible; buffer nxt free

        // issue cp.async for W tile kt+1 (after barrier: nxt no longer being read)
        if (kt + 1 < NKT) {
            #pragma unroll
            for (int j = 0; j < 4; ++j) {
                int nrow = wrow0 + j * 64;
                cp_async16(Wbn + (uint32_t)nrow * (SWROW * 2) + wseg * 16,
                           g_W + (size_t)nrow * KDIM + (kt + 1) * BK + wseg * 8);
            }
            cp_commit();
        }

        // ---- MMAs on tile kt: 4 k-steps of 16 ----
        #pragma unroll
        for (int kk = 0; kk < 4; ++kk) {
            uint32_t a[2][4];
            #pragma unroll
            for (int mt = 0; mt < 2; ++mt)
                ldsm_x4(a[mt][0], a[mt][1], a[mt][2], a[mt][3],
                        Ab + a_lds + mt * 16 * (SA * 2) + kk * 32);
            #pragma unroll
            for (int ntp = 0; ntp < 4; ++ntp) {
                uint32_t b[4];
                ldsm_x4(b[0], b[1], b[2], b[3],
                        Wb + b_lds + ntp * 16 * (SWROW * 2) + kk * 32);
                #pragma unroll
                for (int h = 0; h < 2; ++h) {       // two n-tiles per ldmatrix
                    const int nt = ntp * 2 + h;
                    #pragma unroll
                    for (int mt = 0; mt < 2; ++mt) {
                        asm volatile(
                            "mma.sync.aligned.m16n8k16.row.col.f32.f16.f16.f32 "
                            "{%0,%1,%2,%3}, {%4,%5,%6,%7}, {%8,%9}, {%0,%1,%2,%3};\n"
                            : "+f"(acc[mt][nt][0]), "+f"(acc[mt][nt][1]),
                              "+f"(acc[mt][nt][2]), "+f"(acc[mt][nt][3])
                            : "r"(a[mt][0]), "r"(a[mt][1]), "r"(a[mt][2]), "r"(a[mt][3]),
                              "r"(b[h * 2]), "r"(b[h * 2 + 1]));
                    }
                }
            }
        }

        // ---- stage A tile kt+1 (into nxt buffer; MUFU tanh, short tail) ----
        if (kt + 1 < NKT) {
            float t0 = tanh_fast(xv.x), t1 = tanh_fast(xv.y);
            float t2 = tanh_fast(xv.z), t3 = tanh_fast(xv.w);
            float s0 = t0*t0, s1 = t1*t1, s2 = t2*t2, s3 = t3*t3;
            uint4 c01, c23;
            c01.x = pack_h2(t0, s0); c01.y = pack_h2(s0*t0, s0*s0);
            c01.z = pack_h2(t1, s1); c01.w = pack_h2(s1*t1, s1*s1);
            c23.x = pack_h2(t2, s2); c23.y = pack_h2(s2*t2, s2*s2);
            c23.z = pack_h2(t3, s3); c23.w = pack_h2(s3*t3, s3*s3);
            *(uint4*)((char*)smem + (Abn - sbase) + ast)      = c01;
            *(uint4*)((char*)smem + (Abn - sbase) + ast + 16) = c23;
        }
    }

    // ---- epilogue: + bias, fp32 store ----
    #pragma unroll
    for (int mt = 0; mt < 2; ++mt) {
        int r0 = rowbase + wr * 32 + mt * 16;
        #pragma unroll
        for (int nt = 0; nt < 8; ++nt) {
            int c0 = wc * 64 + nt * 8 + tig * 2;
            float b0 = __ldg(&g_bias[c0]);
            float b1 = __ldg(&g_bias[c0 + 1]);
            int r = r0 + g;
            float2 lo = make_float2(acc[mt][nt][0] + b0, acc[mt][nt][1] + b1);
            float2 hi = make_float2(acc[mt][nt][2] + b0, acc[mt][nt][3] + b1);
            *(float2*)(Y + (size_t)r * OUT_DIM + c0)       = lo;
            *(float2*)(Y + (size_t)(r + 8) * OUT_DIM + c0) = hi;
        }
    }
}

// ---------------------------------------------------------------------------
extern "C" void kernel_launch(void* const* d_in, const int* in_sizes, int n_in,
                              void* d_out, int out_size) {
    const float* x = (const float*)d_in[0];
    const float* coeffs = (const float*)d_in[1];
    if (n_in >= 2 && in_sizes[0] == OUT_DIM * IN_DIM * 6) {  // defensive order check
        coeffs = (const float*)d_in[0];
        x = (const float*)d_in[1];
    }
    float* y = (float*)d_out;

    static bool attr_set = false;
    if (!attr_set) {
        cudaFuncSetAttribute(kan_gemm_kernel,
                             cudaFuncAttributeMaxDynamicSharedMemorySize, SM_TOTAL);
        attr_set = true;
    }

    prep_weights_kernel<<<OUT_DIM, IN_DIM>>>(coeffs);
    kan_gemm_kernel<<<B_ROWS / BM, NTHREADS, SM_TOTAL>>>(x, y);
}